// round 1
// baseline (speedup 1.0000x reference)
#include <cuda_runtime.h>
#include <stdint.h>

#define N_NODES 8192
#define D 128
#define K0 4096
#define K1 2048
#define K2 1024

// ---------------- scratch (static __device__ arrays; no allocs) ----------------
__device__ float               g_score[N_NODES];
__device__ unsigned long long  g_key[N_NODES];
__device__ int                 g_perm0[K0];
__device__ int                 g_perm1[K1];
__device__ int                 g_perm2[K2];
__device__ float               g_xA[N_NODES * D];
__device__ float               g_xB[N_NODES * D];
__device__ float               g_y [N_NODES * D];
__device__ float               g_xs1[K0 * D];
__device__ float               g_xs2[K1 * D];
__device__ float               g_Hg0[(size_t)K0 * K0];
__device__ float               g_Hg1[(size_t)K1 * K1];
__device__ float               g_Hg2[(size_t)K2 * K2];
// split-K partials: max(8 * 8192 * 128, 16 * 4096 * 128) = 8388608 floats (32 MB)
__device__ float               g_part[8388608];

// ---------------- score + sort key ----------------
__global__ void score_key_kernel(const float* __restrict__ x, const float* __restrict__ w,
                                 float* __restrict__ score, unsigned long long* __restrict__ key,
                                 int n) {
    int warp = threadIdx.x >> 5, lane = threadIdx.x & 31;
    int row = blockIdx.x * (blockDim.x >> 5) + warp;
    if (row >= n) return;
    float4 xv = reinterpret_cast<const float4*>(x + (size_t)row * D)[lane];
    float4 wv = reinterpret_cast<const float4*>(w)[lane];
    float d  = xv.x * wv.x + xv.y * wv.y + xv.z * wv.z + xv.w * wv.w;
    float ww = wv.x * wv.x + wv.y * wv.y + wv.z * wv.z + wv.w * wv.w;
    #pragma unroll
    for (int o = 16; o; o >>= 1) {
        d  += __shfl_xor_sync(0xffffffffu, d, o);
        ww += __shfl_xor_sync(0xffffffffu, ww, o);
    }
    if (lane == 0) {
        float s = tanhf(d / sqrtf(ww));
        score[row] = s;
        unsigned int b = __float_as_uint(s);
        // monotonic increasing mapping of float -> uint
        b ^= (b & 0x80000000u) ? 0xFFFFFFFFu : 0x80000000u;
        unsigned int desc = ~b;  // so ascending key sort = descending score
        key[row] = (((unsigned long long)desc) << 32) | (unsigned int)row;
    }
}

// ---------------- single-block bitonic sort (n is a power of two) ----------------
__global__ void bitonic_kernel(unsigned long long* __restrict__ key, int n) {
    extern __shared__ unsigned long long s[];
    for (int i = threadIdx.x; i < n; i += blockDim.x) s[i] = key[i];
    __syncthreads();
    for (int ksz = 2; ksz <= n; ksz <<= 1) {
        for (int j = ksz >> 1; j > 0; j >>= 1) {
            for (int i = threadIdx.x; i < n; i += blockDim.x) {
                int ixj = i ^ j;
                if (ixj > i) {
                    unsigned long long a = s[i], b = s[ixj];
                    bool up = ((i & ksz) == 0);
                    if ((a > b) == up) { s[i] = b; s[ixj] = a; }
                }
            }
            __syncthreads();
        }
    }
    for (int i = threadIdx.x; i < n; i += blockDim.x) key[i] = s[i];
}

// ---------------- gather rows + gate by score, also emit perm ----------------
__global__ void gather_gate_kernel(const float* __restrict__ xin,
                                   const unsigned long long* __restrict__ key,
                                   const float* __restrict__ score,
                                   float* __restrict__ xout, int* __restrict__ perm, int k) {
    int i = blockIdx.x;
    int p = (int)(key[i] & 0xffffffffu);
    if (threadIdx.x == 0) perm[i] = p;
    float s = score[p];
    xout[(size_t)i * D + threadIdx.x] = xin[(size_t)p * D + threadIdx.x] * s;
}

// ---------------- materialize H[perm][:, perm] ----------------
__global__ void gatherH_kernel(const float* __restrict__ H, const int* __restrict__ perm,
                               float* __restrict__ Hg, int k) {
    int i = blockIdx.y;
    int j = blockIdx.x * blockDim.x + threadIdx.x;
    if (j >= k) return;
    int pi = __ldg(&perm[i]);
    int pj = __ldg(&perm[j]);
    Hg[(size_t)i * k + j] = __ldg(&H[(size_t)pi * N_NODES + pj]);
}

// ---------------- Y = X @ W + b   (M x 128) @ (128 x 128) ----------------
__global__ void xw_kernel(const float* __restrict__ X, const float* __restrict__ W,
                          const float* __restrict__ b, float* __restrict__ Y, int M) {
    __shared__ float xs[16][D];
    int r0 = blockIdx.x * 16;
    int tid = threadIdx.x;  // 128
    #pragma unroll
    for (int r = 0; r < 16; r++) xs[r][tid] = X[(size_t)(r0 + r) * D + tid];
    __syncthreads();
    float bv = b[tid];
    float acc[16];
    #pragma unroll
    for (int r = 0; r < 16; r++) acc[r] = bv;
    #pragma unroll 4
    for (int kk = 0; kk < D; kk++) {
        float wv = W[kk * D + tid];
        #pragma unroll
        for (int r = 0; r < 16; r++) acc[r] += xs[r][kk] * wv;
    }
    #pragma unroll
    for (int r = 0; r < 16; r++) Y[(size_t)(r0 + r) * D + tid] = acc[r];
}

// ---------------- Zpart[sk] = A[Mtile x Kc] @ Y[Kc x 128]  (split-K SGEMM) ----------------
#define BM 128
#define BK 16
__global__ void __launch_bounds__(256, 2)
hy_kernel(const float* __restrict__ A, const float* __restrict__ Y,
          float* __restrict__ Zpart, int M, int K, int Kc) {
    __shared__ float As[BK][BM + 4];
    __shared__ float Ys[BK][D];
    int tid = threadIdx.x;
    int rowTile = blockIdx.x * BM;
    int k0 = blockIdx.y * Kc;

    int a_c = (tid & 3) * 4;   // col group (float4) within BK=16
    int a_r = tid >> 2;        // 64 rows per pass, 2 passes
    int y_n = (tid & 31) * 4;  // float4 col in [0,128)
    int y_k = tid >> 5;        // 8 k-rows per pass, 2 passes

    int rb = (tid >> 4) * 8;
    int cb = (tid & 15) * 8;

    float acc[8][8];
    #pragma unroll
    for (int i = 0; i < 8; i++)
        #pragma unroll
        for (int j = 0; j < 8; j++) acc[i][j] = 0.f;

    for (int kk = k0; kk < k0 + Kc; kk += BK) {
        #pragma unroll
        for (int p = 0; p < 2; p++) {
            int r = a_r + p * 64;
            float4 v = *reinterpret_cast<const float4*>(&A[(size_t)(rowTile + r) * K + kk + a_c]);
            As[a_c + 0][r] = v.x;
            As[a_c + 1][r] = v.y;
            As[a_c + 2][r] = v.z;
            As[a_c + 3][r] = v.w;
        }
        #pragma unroll
        for (int p = 0; p < 2; p++) {
            int kr = y_k + p * 8;
            *reinterpret_cast<float4*>(&Ys[kr][y_n]) =
                *reinterpret_cast<const float4*>(&Y[(size_t)(kk + kr) * D + y_n]);
        }
        __syncthreads();
        #pragma unroll
        for (int k = 0; k < BK; k++) {
            float4 a0 = *reinterpret_cast<const float4*>(&As[k][rb]);
            float4 a1 = *reinterpret_cast<const float4*>(&As[k][rb + 4]);
            float4 b0 = *reinterpret_cast<const float4*>(&Ys[k][cb]);
            float4 b1 = *reinterpret_cast<const float4*>(&Ys[k][cb + 4]);
            float av[8] = {a0.x, a0.y, a0.z, a0.w, a1.x, a1.y, a1.z, a1.w};
            float bv[8] = {b0.x, b0.y, b0.z, b0.w, b1.x, b1.y, b1.z, b1.w};
            #pragma unroll
            for (int i = 0; i < 8; i++)
                #pragma unroll
                for (int j = 0; j < 8; j++) acc[i][j] += av[i] * bv[j];
        }
        __syncthreads();
    }

    float* Zp = Zpart + (size_t)blockIdx.y * M * D;
    #pragma unroll
    for (int i = 0; i < 8; i++) {
        float4 v0 = make_float4(acc[i][0], acc[i][1], acc[i][2], acc[i][3]);
        float4 v1 = make_float4(acc[i][4], acc[i][5], acc[i][6], acc[i][7]);
        *reinterpret_cast<float4*>(&Zp[(size_t)(rowTile + rb + i) * D + cb])     = v0;
        *reinterpret_cast<float4*>(&Zp[(size_t)(rowTile + rb + i) * D + cb + 4]) = v1;
    }
}

// ---------------- deterministic partial reduction + relu ----------------
__global__ void reduce_relu_kernel(const float* __restrict__ Zpart, float* __restrict__ Z,
                                   int total, int SK) {
    int i = blockIdx.x * blockDim.x + threadIdx.x;
    if (i >= total) return;
    float s = 0.f;
    for (int p = 0; p < SK; p++) s += Zpart[(size_t)p * total + i];
    Z[i] = fmaxf(s, 0.f);
}

// ---------------- dst[perm[i]] += x[i] ----------------
__global__ void scatter_add_kernel(float* __restrict__ dst, const float* __restrict__ xsrc,
                                   const int* __restrict__ perm, int k) {
    int i = blockIdx.x;
    int p = perm[i];
    dst[(size_t)p * D + threadIdx.x] += xsrc[(size_t)i * D + threadIdx.x];
}

// ---------------- host orchestration ----------------
static inline int pick_sk(int M) { return (M >= 8192) ? 8 : 16; }

static void conv_relu(const float* A, const float* X, const float* W, const float* b,
                      float* out, int M, int Kdim, float* y, float* part) {
    xw_kernel<<<M / 16, 128>>>(X, W, b, y, M);
    int SK = pick_sk(M);
    int Kc = Kdim / SK;
    dim3 grid(M / BM, SK);
    hy_kernel<<<grid, 256>>>(A, y, part, M, Kdim, Kc);
    int total = M * D;
    reduce_relu_kernel<<<(total + 255) / 256, 256>>>(part, out, total, SK);
}

extern "C" void kernel_launch(void* const* d_in, const int* in_sizes, int n_in,
                              void* d_out, int out_size) {
    const float* feat = (const float*)d_in[0];
    const float* H    = (const float*)d_in[1];
    const float* pw[3] = {(const float*)d_in[2], (const float*)d_in[3], (const float*)d_in[4]};
    const float* Wd[3] = {(const float*)d_in[5], (const float*)d_in[7], (const float*)d_in[9]};
    const float* bd[3] = {(const float*)d_in[6], (const float*)d_in[8], (const float*)d_in[10]};
    const float* Wu[3] = {(const float*)d_in[11], (const float*)d_in[13], (const float*)d_in[15]};
    const float* bu[3] = {(const float*)d_in[12], (const float*)d_in[14], (const float*)d_in[16]};
    float* out = (float*)d_out;

    float *score, *xA, *xB, *y, *xs1, *xs2, *Hg0, *Hg1, *Hg2, *part;
    unsigned long long* key;
    int *perm0, *perm1, *perm2;
    cudaGetSymbolAddress((void**)&score, g_score);
    cudaGetSymbolAddress((void**)&key,   g_key);
    cudaGetSymbolAddress((void**)&perm0, g_perm0);
    cudaGetSymbolAddress((void**)&perm1, g_perm1);
    cudaGetSymbolAddress((void**)&perm2, g_perm2);
    cudaGetSymbolAddress((void**)&xA,    g_xA);
    cudaGetSymbolAddress((void**)&xB,    g_xB);
    cudaGetSymbolAddress((void**)&y,     g_y);
    cudaGetSymbolAddress((void**)&xs1,   g_xs1);
    cudaGetSymbolAddress((void**)&xs2,   g_xs2);
    cudaGetSymbolAddress((void**)&Hg0,   g_Hg0);
    cudaGetSymbolAddress((void**)&Hg1,   g_Hg1);
    cudaGetSymbolAddress((void**)&Hg2,   g_Hg2);
    cudaGetSymbolAddress((void**)&part,  g_part);

    cudaFuncSetAttribute(bitonic_kernel, cudaFuncAttributeMaxDynamicSharedMemorySize, 65536);

    // ---------------- DOWN level 0 : n=8192 -> k=4096 ----------------
    score_key_kernel<<<N_NODES / 4, 128>>>(feat, pw[0], score, key, N_NODES);
    bitonic_kernel<<<1, 1024, N_NODES * 8>>>(key, N_NODES);
    gather_gate_kernel<<<K0, 128>>>(feat, key, score, xA, perm0, K0);
    gatherH_kernel<<<dim3(K0 / 256, K0), 256>>>(H, perm0, Hg0, K0);
    conv_relu(Hg0, xA, Wd[0], bd[0], xs1, K0, K0, y, part);   // xsaved[1]

    // ---------------- DOWN level 1 : n=4096 -> k=2048 ----------------
    score_key_kernel<<<K0 / 4, 128>>>(xs1, pw[1], score, key, K0);
    bitonic_kernel<<<1, 1024, K0 * 8>>>(key, K0);
    gather_gate_kernel<<<K1, 128>>>(xs1, key, score, xA, perm1, K1);
    gatherH_kernel<<<dim3(K1 / 256, K1), 256>>>(H, perm1, Hg1, K1);  // full-H index (bug preserved)
    conv_relu(Hg1, xA, Wd[1], bd[1], xs2, K1, K1, y, part);   // xsaved[2]

    // ---------------- DOWN level 2 : n=2048 -> k=1024 ----------------
    score_key_kernel<<<K1 / 4, 128>>>(xs2, pw[2], score, key, K1);
    bitonic_kernel<<<1, 1024, K1 * 8>>>(key, K1);
    gather_gate_kernel<<<K2, 128>>>(xs2, key, score, xA, perm2, K2);
    gatherH_kernel<<<dim3(K2 / 256, K2), 256>>>(H, perm2, Hg2, K2);
    conv_relu(Hg2, xA, Wd[2], bd[2], xB, K2, K2, y, part);    // current x (1024 x 128)

    // ---------------- UP i=0 (j=2): res=xs2(2048), graph=Hg1, perm2 ----------------
    cudaMemcpyAsync(xA, xs2, (size_t)K1 * D * sizeof(float), cudaMemcpyDeviceToDevice);
    scatter_add_kernel<<<K2, 128>>>(xA, xB, perm2, K2);
    conv_relu(Hg1, xA, Wu[0], bu[0], xB, K1, K1, y, part);

    // ---------------- UP i=1 (j=1): res=xs1(4096), graph=Hg0, perm1 ----------------
    cudaMemcpyAsync(xA, xs1, (size_t)K0 * D * sizeof(float), cudaMemcpyDeviceToDevice);
    scatter_add_kernel<<<K1, 128>>>(xA, xB, perm1, K1);
    conv_relu(Hg0, xA, Wu[1], bu[1], xB, K0, K0, y, part);

    // ---------------- UP i=2 (j=0): res=feat(8192), graph=H, perm0 ----------------
    cudaMemcpyAsync(xA, feat, (size_t)N_NODES * D * sizeof(float), cudaMemcpyDeviceToDevice);
    scatter_add_kernel<<<K0, 128>>>(xA, xB, perm0, K0);
    conv_relu(H, xA, Wu[2], bu[2], out, N_NODES, N_NODES, y, part);
}

// round 3
// speedup vs baseline: 1.4355x; 1.4355x over previous
#include <cuda_runtime.h>
#include <cuda_bf16.h>
#include <stdint.h>

#define N_NODES 8192
#define D 128
#define K0 4096
#define K1 2048
#define K2 1024

// GEMM tile config
#define BM 128
#define BN 128
#define BK 32
#define TSTRIDE 40                       // halfs per smem tile row (32 + 8 pad)
#define TILE_B (128 * TSTRIDE * 2)       // 10240 bytes per tile plane
#define STAGE_B (4 * TILE_B)             // Ah, Al, Bh, Bl
#define GEMM_DYN (2 * STAGE_B + 256)

// ---------------- scratch (static __device__ arrays; no allocs) ----------------
__device__ __align__(256) float               g_score[N_NODES];
__device__ __align__(256) unsigned long long  g_key[N_NODES];
__device__ __align__(256) int                 g_perm0[K0];
__device__ __align__(256) int                 g_perm1[K1];
__device__ __align__(256) int                 g_perm2[K2];
__device__ __align__(256) float               g_xA[N_NODES * D];
__device__ __align__(256) float               g_xB[N_NODES * D];
__device__ __align__(256) float               g_xs1[K0 * D];
__device__ __align__(256) float               g_xs2[K1 * D];
__device__ __align__(256) __nv_bfloat16       g_Hg0h[(size_t)K0 * K0];
__device__ __align__(256) __nv_bfloat16       g_Hg0l[(size_t)K0 * K0];
__device__ __align__(256) __nv_bfloat16       g_Hg1h[(size_t)K1 * K1];
__device__ __align__(256) __nv_bfloat16       g_Hg1l[(size_t)K1 * K1];
__device__ __align__(256) __nv_bfloat16       g_Hg2h[(size_t)K2 * K2];
__device__ __align__(256) __nv_bfloat16       g_Hg2l[(size_t)K2 * K2];
__device__ __align__(256) float               g_part[4 * 1024 * 1024];  // >= S*n*D
__device__ __align__(256) __nv_bfloat16       g_yth[D * N_NODES];
__device__ __align__(256) __nv_bfloat16       g_ytl[D * N_NODES];

// ---------------- PTX helpers ----------------
__device__ __forceinline__ uint32_t smem_u32(const void* p) {
    uint32_t a;
    asm("{ .reg .u64 t; cvta.to.shared.u64 t, %1; cvt.u32.u64 %0, t; }" : "=r"(a) : "l"(p));
    return a;
}
__device__ __forceinline__ void cpasync16(uint32_t dst, const void* src) {
    asm volatile("cp.async.cg.shared.global [%0], [%1], 16;" :: "r"(dst), "l"(src));
}
__device__ __forceinline__ void ldsm4(uint32_t* r, uint32_t a) {
    asm volatile("ldmatrix.sync.aligned.m8n8.x4.shared.b16 {%0,%1,%2,%3}, [%4];"
                 : "=r"(r[0]), "=r"(r[1]), "=r"(r[2]), "=r"(r[3]) : "r"(a));
}
__device__ __forceinline__ void mma_bf16(float* c, const uint32_t* a, uint32_t b0, uint32_t b1) {
    asm volatile("mma.sync.aligned.m16n8k16.row.col.f32.bf16.bf16.f32 "
                 "{%0,%1,%2,%3}, {%4,%5,%6,%7}, {%8,%9}, {%0,%1,%2,%3};"
                 : "+f"(c[0]), "+f"(c[1]), "+f"(c[2]), "+f"(c[3])
                 : "r"(a[0]), "r"(a[1]), "r"(a[2]), "r"(a[3]), "r"(b0), "r"(b1));
}
__device__ __forceinline__ uint32_t pack_bf16x2(float a, float b) {
    __nv_bfloat162 t = __floats2bfloat162_rn(a, b);
    return *reinterpret_cast<uint32_t*>(&t);
}

// ---------------- score + sort key ----------------
__global__ void score_key_kernel(const float* __restrict__ x, const float* __restrict__ w,
                                 float* __restrict__ score, unsigned long long* __restrict__ key,
                                 int n) {
    int warp = threadIdx.x >> 5, lane = threadIdx.x & 31;
    int row = blockIdx.x * (blockDim.x >> 5) + warp;
    if (row >= n) return;
    float4 xv = reinterpret_cast<const float4*>(x + (size_t)row * D)[lane];
    float4 wv = reinterpret_cast<const float4*>(w)[lane];
    float d  = xv.x * wv.x + xv.y * wv.y + xv.z * wv.z + xv.w * wv.w;
    float ww = wv.x * wv.x + wv.y * wv.y + wv.z * wv.z + wv.w * wv.w;
    #pragma unroll
    for (int o = 16; o; o >>= 1) {
        d  += __shfl_xor_sync(0xffffffffu, d, o);
        ww += __shfl_xor_sync(0xffffffffu, ww, o);
    }
    if (lane == 0) {
        float s = tanhf(d / sqrtf(ww));
        score[row] = s;
        unsigned int b = __float_as_uint(s);
        b ^= (b & 0x80000000u) ? 0xFFFFFFFFu : 0x80000000u;
        unsigned int desc = ~b;
        key[row] = (((unsigned long long)desc) << 32) | (unsigned int)row;
    }
}

// ---------------- single-block bitonic sort ----------------
__global__ void bitonic_kernel(unsigned long long* __restrict__ key, int n) {
    extern __shared__ unsigned long long s[];
    for (int i = threadIdx.x; i < n; i += blockDim.x) s[i] = key[i];
    __syncthreads();
    for (int ksz = 2; ksz <= n; ksz <<= 1) {
        for (int j = ksz >> 1; j > 0; j >>= 1) {
            for (int i = threadIdx.x; i < n; i += blockDim.x) {
                int ixj = i ^ j;
                if (ixj > i) {
                    unsigned long long a = s[i], b = s[ixj];
                    bool up = ((i & ksz) == 0);
                    if ((a > b) == up) { s[i] = b; s[ixj] = a; }
                }
            }
            __syncthreads();
        }
    }
    for (int i = threadIdx.x; i < n; i += blockDim.x) key[i] = s[i];
}

// ---------------- gather rows + gate by score, emit perm ----------------
__global__ void gather_gate_kernel(const float* __restrict__ xin,
                                   const unsigned long long* __restrict__ key,
                                   const float* __restrict__ score,
                                   float* __restrict__ xout, int* __restrict__ perm, int k) {
    int i = blockIdx.x;
    int p = (int)(key[i] & 0xffffffffu);
    if (threadIdx.x == 0) perm[i] = p;
    float s = score[p];
    xout[(size_t)i * D + threadIdx.x] = xin[(size_t)p * D + threadIdx.x] * s;
}

// ---------------- H[perm][:,perm] -> bf16 hi/lo planes, row staging ----------------
__global__ void gatherH_rows(const float* __restrict__ H, const int* __restrict__ perm,
                             __nv_bfloat16* __restrict__ Hh, __nv_bfloat16* __restrict__ Hl,
                             int k) {
    extern __shared__ float sm[];
    float* rowf = sm;
    int* ps = (int*)(sm + N_NODES);
    int i = blockIdx.x;
    int pi = __ldg(&perm[i]);
    const float4* src = reinterpret_cast<const float4*>(H + (size_t)pi * N_NODES);
    float4* d4 = reinterpret_cast<float4*>(rowf);
    for (int j = threadIdx.x; j < N_NODES / 4; j += blockDim.x) d4[j] = src[j];
    for (int j = threadIdx.x; j < k; j += blockDim.x) ps[j] = __ldg(&perm[j]);
    __syncthreads();
    __nv_bfloat16* dh = Hh + (size_t)i * k;
    __nv_bfloat16* dl = Hl + (size_t)i * k;
    for (int j = threadIdx.x; j < k; j += blockDim.x) {
        float v = rowf[ps[j]];
        __nv_bfloat16 h = __float2bfloat16(v);
        dh[j] = h;
        dl[j] = __float2bfloat16(v - __bfloat162float(h));
    }
}

// ---------------- Yt = (X @ W + b)^T as bf16 hi/lo planes [128 x n] ----------------
__global__ void xw_trans_kernel(const float* __restrict__ X, const float* __restrict__ W,
                                const float* __restrict__ b,
                                __nv_bfloat16* __restrict__ Yh, __nv_bfloat16* __restrict__ Yl,
                                int n) {
    __shared__ float xs[16][D];
    int r0 = blockIdx.x * 16;
    int tid = threadIdx.x;
    #pragma unroll
    for (int r = 0; r < 16; r++) xs[r][tid] = X[(size_t)(r0 + r) * D + tid];
    __syncthreads();
    float bv = b[tid];
    float acc[16];
    #pragma unroll
    for (int r = 0; r < 16; r++) acc[r] = bv;
    #pragma unroll 4
    for (int kk = 0; kk < D; kk++) {
        float wv = W[kk * D + tid];
        #pragma unroll
        for (int r = 0; r < 16; r++) acc[r] += xs[r][kk] * wv;
    }
    #pragma unroll
    for (int r = 0; r < 16; r++) {
        float v = acc[r];
        __nv_bfloat16 h = __float2bfloat16(v);
        Yh[(size_t)tid * n + r0 + r] = h;
        Yl[(size_t)tid * n + r0 + r] = __float2bfloat16(v - __bfloat162float(h));
    }
}

// ---------------- mma.sync bf16 3-chain split-K GEMM ----------------
// part[blockIdx.y] (+)= A[128-row tile, Kc slice] @ Y  (Y given as K-major planes Bh/Bl [128 x n])
// CONV=true : A is fp32 in global (full H), converted in-kernel.
// CONV=false: A given as bf16 hi/lo planes (gathered H).
template <bool CONV>
__global__ void __launch_bounds__(256, 1)
mma_gemm(const float* __restrict__ Afp,
         const __nv_bfloat16* __restrict__ Ahp, const __nv_bfloat16* __restrict__ Alp,
         const __nv_bfloat16* __restrict__ Bhp, const __nv_bfloat16* __restrict__ Blp,
         float* __restrict__ part, int n, int Kc) {
    extern __shared__ char dyn[];
    uint32_t base = (smem_u32(dyn) + 127) & ~127u;

    const int tid = threadIdx.x, lane = tid & 31, wid = tid >> 5;
    const int warp_m = wid & 3, warp_n = wid >> 2;
    const int rowTile = blockIdx.x * BM;
    const int kbase = blockIdx.y * Kc;
    const int nc = Kc / BK;

    const uint32_t oAh = 0, oAl = TILE_B, oBh = 2 * TILE_B, oBl = 3 * TILE_B;

    // A convert-path register staging
    const int a_row = tid >> 1;
    const int a_kh  = (tid & 1) * 16;
    float4 av[4];

    // B cp.async mapping: 2 chunks of 16B per thread per plane
    const int bj0 = (tid * 2) >> 2;          // row for chunk 0
    const int bc0 = ((tid * 2) & 3) * 8;     // k offset (halfs)
    const int bj1 = (tid * 2 + 1) >> 2;
    const int bc1 = ((tid * 2 + 1) & 3) * 8;

    auto issue_stage = [&](int c) {
        uint32_t sb = base + (uint32_t)(c & 1) * STAGE_B;
        int kk = kbase + c * BK;
        cpasync16(sb + oBh + bj0 * (TSTRIDE * 2) + bc0 * 2, Bhp + (size_t)bj0 * n + kk + bc0);
        cpasync16(sb + oBh + bj1 * (TSTRIDE * 2) + bc1 * 2, Bhp + (size_t)bj1 * n + kk + bc1);
        cpasync16(sb + oBl + bj0 * (TSTRIDE * 2) + bc0 * 2, Blp + (size_t)bj0 * n + kk + bc0);
        cpasync16(sb + oBl + bj1 * (TSTRIDE * 2) + bc1 * 2, Blp + (size_t)bj1 * n + kk + bc1);
        if (!CONV) {
            cpasync16(sb + oAh + bj0 * (TSTRIDE * 2) + bc0 * 2, Ahp + (size_t)(rowTile + bj0) * n + kk + bc0);
            cpasync16(sb + oAh + bj1 * (TSTRIDE * 2) + bc1 * 2, Ahp + (size_t)(rowTile + bj1) * n + kk + bc1);
            cpasync16(sb + oAl + bj0 * (TSTRIDE * 2) + bc0 * 2, Alp + (size_t)(rowTile + bj0) * n + kk + bc0);
            cpasync16(sb + oAl + bj1 * (TSTRIDE * 2) + bc1 * 2, Alp + (size_t)(rowTile + bj1) * n + kk + bc1);
        }
        asm volatile("cp.async.commit_group;");
    };
    auto ldg_A = [&](int c) {
        if (CONV) {
            const float4* p = reinterpret_cast<const float4*>(
                Afp + (size_t)(rowTile + a_row) * n + kbase + c * BK + a_kh);
            #pragma unroll
            for (int q = 0; q < 4; q++) av[q] = p[q];
        }
    };
    auto sts_A = [&](int c) {
        if (CONV) {
            uint32_t sb = base + (uint32_t)(c & 1) * STAGE_B;
            uint32_t h[8], l[8];
            #pragma unroll
            for (int q = 0; q < 4; q++) {
                float hx = __bfloat162float(__float2bfloat16(av[q].x));
                float hy = __bfloat162float(__float2bfloat16(av[q].y));
                float hz = __bfloat162float(__float2bfloat16(av[q].z));
                float hw = __bfloat162float(__float2bfloat16(av[q].w));
                h[q * 2]     = pack_bf16x2(av[q].x, av[q].y);
                h[q * 2 + 1] = pack_bf16x2(av[q].z, av[q].w);
                l[q * 2]     = pack_bf16x2(av[q].x - hx, av[q].y - hy);
                l[q * 2 + 1] = pack_bf16x2(av[q].z - hz, av[q].w - hw);
            }
            uint32_t off = a_row * (TSTRIDE * 2) + a_kh * 2;
            asm volatile("st.shared.v4.b32 [%0], {%1,%2,%3,%4};"
                         :: "r"(sb + oAh + off), "r"(h[0]), "r"(h[1]), "r"(h[2]), "r"(h[3]));
            asm volatile("st.shared.v4.b32 [%0], {%1,%2,%3,%4};"
                         :: "r"(sb + oAh + off + 16), "r"(h[4]), "r"(h[5]), "r"(h[6]), "r"(h[7]));
            asm volatile("st.shared.v4.b32 [%0], {%1,%2,%3,%4};"
                         :: "r"(sb + oAl + off), "r"(l[0]), "r"(l[1]), "r"(l[2]), "r"(l[3]));
            asm volatile("st.shared.v4.b32 [%0], {%1,%2,%3,%4};"
                         :: "r"(sb + oAl + off + 16), "r"(l[4]), "r"(l[5]), "r"(l[6]), "r"(l[7]));
        }
    };

    float acc[2][8][4];
    #pragma unroll
    for (int i = 0; i < 2; i++)
        #pragma unroll
        for (int j = 0; j < 8; j++)
            #pragma unroll
            for (int q = 0; q < 4; q++) acc[i][j][q] = 0.f;

    // ldmatrix per-lane address pieces
    const int lr = lane & 7, lsel = lane >> 3;

    // prologue: stage 0
    issue_stage(0);
    ldg_A(0);
    sts_A(0);

    for (int c = 0; c < nc; c++) {
        uint32_t sb = base + (uint32_t)(c & 1) * STAGE_B;
        bool pf = (c + 1 < nc);
        __syncthreads();                 // all warps done with buf c^1
        if (pf) { issue_stage(c + 1); ldg_A(c + 1); }
        if (pf) asm volatile("cp.async.wait_group 1;" ::: "memory");
        else    asm volatile("cp.async.wait_group 0;" ::: "memory");
        __syncthreads();                 // stage c visible

        #pragma unroll
        for (int ks = 0; ks < 2; ks++) {
            const int k16 = ks * 16;
            uint32_t Ahf[2][4], Alf[2][4], Bhf[4][4], Blf[4][4];
            #pragma unroll
            for (int mf = 0; mf < 2; mf++) {
                int row = warp_m * 32 + mf * 16 + lr + (lsel & 1) * 8;
                int col = k16 + (lsel >> 1) * 8;
                uint32_t off = row * (TSTRIDE * 2) + col * 2;
                ldsm4(Ahf[mf], sb + oAh + off);
                ldsm4(Alf[mf], sb + oAl + off);
            }
            #pragma unroll
            for (int p = 0; p < 4; p++) {
                int row = warp_n * 64 + p * 16 + lr + (lsel >> 1) * 8;
                int col = k16 + (lsel & 1) * 8;
                uint32_t off = row * (TSTRIDE * 2) + col * 2;
                ldsm4(Bhf[p], sb + oBh + off);
                ldsm4(Blf[p], sb + oBl + off);
            }
            #pragma unroll
            for (int mf = 0; mf < 2; mf++)
                #pragma unroll
                for (int nf = 0; nf < 8; nf++) {
                    uint32_t bh0 = Bhf[nf >> 1][(nf & 1) * 2];
                    uint32_t bh1 = Bhf[nf >> 1][(nf & 1) * 2 + 1];
                    uint32_t bl0 = Blf[nf >> 1][(nf & 1) * 2];
                    uint32_t bl1 = Blf[nf >> 1][(nf & 1) * 2 + 1];
                    mma_bf16(acc[mf][nf], Ahf[mf], bh0, bh1);
                    mma_bf16(acc[mf][nf], Ahf[mf], bl0, bl1);
                    mma_bf16(acc[mf][nf], Alf[mf], bh0, bh1);
                }
        }
        if (pf) sts_A(c + 1);
    }

    // epilogue: fp32 partials
    float* Zp = part + (size_t)blockIdx.y * n * D;
    const int g = lane >> 2, cq = (lane & 3) * 2;
    #pragma unroll
    for (int mf = 0; mf < 2; mf++) {
        int row = rowTile + warp_m * 32 + mf * 16 + g;
        #pragma unroll
        for (int nf = 0; nf < 8; nf++) {
            int col = warp_n * 64 + nf * 8 + cq;
            *reinterpret_cast<float2*>(&Zp[(size_t)row * D + col]) =
                make_float2(acc[mf][nf][0], acc[mf][nf][1]);
            *reinterpret_cast<float2*>(&Zp[(size_t)(row + 8) * D + col]) =
                make_float2(acc[mf][nf][2], acc[mf][nf][3]);
        }
    }
}

// ---------------- deterministic partial reduction + relu ----------------
__global__ void reduce_relu_kernel(const float* __restrict__ Zpart, float* __restrict__ Z,
                                   int total, int SK) {
    int i = blockIdx.x * blockDim.x + threadIdx.x;
    if (i >= total) return;
    float s = 0.f;
    for (int p = 0; p < SK; p++) s += Zpart[(size_t)p * total + i];
    Z[i] = fmaxf(s, 0.f);
}

// ---------------- dst[perm[i]] += x[i] ----------------
__global__ void scatter_add_kernel(float* __restrict__ dst, const float* __restrict__ xsrc,
                                   const int* __restrict__ perm, int k) {
    int i = blockIdx.x;
    int p = perm[i];
    dst[(size_t)p * D + threadIdx.x] += xsrc[(size_t)i * D + threadIdx.x];
}

// ---------------- host orchestration ----------------
static inline int pick_sk(int n) {
    if (n >= 8192) return 2;
    if (n >= 4096) return 4;
    if (n >= 2048) return 8;
    return 16;
}

static void conv_relu(const float* Afp, const __nv_bfloat16* Ahp, const __nv_bfloat16* Alp,
                      const float* X, const float* W, const float* bias,
                      float* outp, int n, __nv_bfloat16* yth, __nv_bfloat16* ytl, float* part) {
    xw_trans_kernel<<<n / 16, 128>>>(X, W, bias, yth, ytl, n);
    int S = pick_sk(n);
    dim3 grid(n / BM, S);
    if (Afp)
        mma_gemm<true><<<grid, 256, GEMM_DYN>>>(Afp, nullptr, nullptr, yth, ytl, part, n, n / S);
    else
        mma_gemm<false><<<grid, 256, GEMM_DYN>>>(nullptr, Ahp, Alp, yth, ytl, part, n, n / S);
    int total = n * D;
    reduce_relu_kernel<<<(total + 255) / 256, 256>>>(part, outp, total, S);
}

extern "C" void kernel_launch(void* const* d_in, const int* in_sizes, int n_in,
                              void* d_out, int out_size) {
    const float* feat = (const float*)d_in[0];
    const float* H    = (const float*)d_in[1];
    const float* pw[3] = {(const float*)d_in[2], (const float*)d_in[3], (const float*)d_in[4]};
    const float* Wd[3] = {(const float*)d_in[5], (const float*)d_in[7], (const float*)d_in[9]};
    const float* bd[3] = {(const float*)d_in[6], (const float*)d_in[8], (const float*)d_in[10]};
    const float* Wu[3] = {(const float*)d_in[11], (const float*)d_in[13], (const float*)d_in[15]};
    const float* bu[3] = {(const float*)d_in[12], (const float*)d_in[14], (const float*)d_in[16]};
    float* out = (float*)d_out;

    float *score, *xA, *xB, *xs1, *xs2, *part;
    unsigned long long* key;
    int *perm0, *perm1, *perm2;
    __nv_bfloat16 *yth, *ytl, *Hg0h, *Hg0l, *Hg1h, *Hg1l, *Hg2h, *Hg2l;
    cudaGetSymbolAddress((void**)&score, g_score);
    cudaGetSymbolAddress((void**)&key,   g_key);
    cudaGetSymbolAddress((void**)&perm0, g_perm0);
    cudaGetSymbolAddress((void**)&perm1, g_perm1);
    cudaGetSymbolAddress((void**)&perm2, g_perm2);
    cudaGetSymbolAddress((void**)&xA,    g_xA);
    cudaGetSymbolAddress((void**)&xB,    g_xB);
    cudaGetSymbolAddress((void**)&xs1,   g_xs1);
    cudaGetSymbolAddress((void**)&xs2,   g_xs2);
    cudaGetSymbolAddress((void**)&part,  g_part);
    cudaGetSymbolAddress((void**)&yth,   g_yth);
    cudaGetSymbolAddress((void**)&ytl,   g_ytl);
    cudaGetSymbolAddress((void**)&Hg0h,  g_Hg0h);
    cudaGetSymbolAddress((void**)&Hg0l,  g_Hg0l);
    cudaGetSymbolAddress((void**)&Hg1h,  g_Hg1h);
    cudaGetSymbolAddress((void**)&Hg1l,  g_Hg1l);
    cudaGetSymbolAddress((void**)&Hg2h,  g_Hg2h);
    cudaGetSymbolAddress((void**)&Hg2l,  g_Hg2l);

    cudaFuncSetAttribute(bitonic_kernel, cudaFuncAttributeMaxDynamicSharedMemorySize, 65536);
    cudaFuncSetAttribute(gatherH_rows,   cudaFuncAttributeMaxDynamicSharedMemorySize, 65536);
    cudaFuncSetAttribute(mma_gemm<true>,  cudaFuncAttributeMaxDynamicSharedMemorySize, GEMM_DYN);
    cudaFuncSetAttribute(mma_gemm<false>, cudaFuncAttributeMaxDynamicSharedMemorySize, GEMM_DYN);

    // ---------------- DOWN level 0 : n=8192 -> k=4096 ----------------
    score_key_kernel<<<N_NODES / 4, 128>>>(feat, pw[0], score, key, N_NODES);
    bitonic_kernel<<<1, 1024, N_NODES * 8>>>(key, N_NODES);
    gather_gate_kernel<<<K0, 128>>>(feat, key, score, xA, perm0, K0);
    gatherH_rows<<<K0, 256, (N_NODES + K0) * 4>>>(H, perm0, Hg0h, Hg0l, K0);
    conv_relu(nullptr, Hg0h, Hg0l, xA, Wd[0], bd[0], xs1, K0, yth, ytl, part);

    // ---------------- DOWN level 1 : n=4096 -> k=2048 ----------------
    score_key_kernel<<<K0 / 4, 128>>>(xs1, pw[1], score, key, K0);
    bitonic_kernel<<<1, 1024, K0 * 8>>>(key, K0);
    gather_gate_kernel<<<K1, 128>>>(xs1, key, score, xA, perm1, K1);
    gatherH_rows<<<K1, 256, (N_NODES + K1) * 4>>>(H, perm1, Hg1h, Hg1l, K1);  // full-H index (bug preserved)
    conv_relu(nullptr, Hg1h, Hg1l, xA, Wd[1], bd[1], xs2, K1, yth, ytl, part);

    // ---------------- DOWN level 2 : n=2048 -> k=1024 ----------------
    score_key_kernel<<<K1 / 4, 128>>>(xs2, pw[2], score, key, K1);
    bitonic_kernel<<<1, 1024, K1 * 8>>>(key, K1);
    gather_gate_kernel<<<K2, 128>>>(xs2, key, score, xA, perm2, K2);
    gatherH_rows<<<K2, 256, (N_NODES + K2) * 4>>>(H, perm2, Hg2h, Hg2l, K2);
    conv_relu(nullptr, Hg2h, Hg2l, xA, Wd[2], bd[2], xB, K2, yth, ytl, part);

    // ---------------- UP i=0 (j=2): res=xs2(2048), graph=Hg1, perm2 ----------------
    cudaMemcpyAsync(xA, xs2, (size_t)K1 * D * sizeof(float), cudaMemcpyDeviceToDevice);
    scatter_add_kernel<<<K2, 128>>>(xA, xB, perm2, K2);
    conv_relu(nullptr, Hg1h, Hg1l, xA, Wu[0], bu[0], xB, K1, yth, ytl, part);

    // ---------------- UP i=1 (j=1): res=xs1(4096), graph=Hg0, perm1 ----------------
    cudaMemcpyAsync(xA, xs1, (size_t)K0 * D * sizeof(float), cudaMemcpyDeviceToDevice);
    scatter_add_kernel<<<K1, 128>>>(xA, xB, perm1, K1);
    conv_relu(nullptr, Hg0h, Hg0l, xA, Wu[1], bu[1], xB, K0, yth, ytl, part);

    // ---------------- UP i=2 (j=0): res=feat(8192), graph=H (fp32, convert), perm0 ----------------
    cudaMemcpyAsync(xA, feat, (size_t)N_NODES * D * sizeof(float), cudaMemcpyDeviceToDevice);
    scatter_add_kernel<<<K0, 128>>>(xA, xB, perm0, K0);
    conv_relu(H, nullptr, nullptr, xA, Wu[2], bu[2], out, N_NODES, yth, ytl, part);
}

// round 4
// speedup vs baseline: 1.4986x; 1.0439x over previous
#include <cuda_runtime.h>
#include <cuda_bf16.h>
#include <stdint.h>

#define N_NODES 8192
#define D 128
#define K0 4096
#define K1 2048
#define K2 1024

// GEMM tile config
#define BM 128
#define BN 128
#define BK 32
#define TSTRIDE 40                       // halfs per smem tile row (32 + 8 pad)
#define TILE_B (128 * TSTRIDE * 2)       // 10240 bytes per tile plane
#define STAGE_B (4 * TILE_B)             // Ah, Al, Bh, Bl
#define GEMM_DYN (2 * STAGE_B + 256)

// ---------------- scratch (static __device__ arrays; no allocs) ----------------
__device__ __align__(256) float               g_score[N_NODES];
__device__ __align__(256) unsigned long long  g_key[N_NODES];
__device__ __align__(256) int                 g_perm0[K0];
__device__ __align__(256) int                 g_perm1[K1];
__device__ __align__(256) int                 g_perm2[K2];
__device__ __align__(256) float               g_xA[N_NODES * D];
__device__ __align__(256) float               g_xB[N_NODES * D];
__device__ __align__(256) float               g_xs1[K0 * D];
__device__ __align__(256) float               g_xs2[K1 * D];
__device__ __align__(256) __nv_bfloat16       g_Hg0h[(size_t)K0 * K0];
__device__ __align__(256) __nv_bfloat16       g_Hg0l[(size_t)K0 * K0];
__device__ __align__(256) __nv_bfloat16       g_Hg1h[(size_t)K1 * K1];
__device__ __align__(256) __nv_bfloat16       g_Hg1l[(size_t)K1 * K1];
__device__ __align__(256) __nv_bfloat16       g_Hg2h[(size_t)K2 * K2];
__device__ __align__(256) __nv_bfloat16       g_Hg2l[(size_t)K2 * K2];
__device__ __align__(256) float               g_part[4 * 1024 * 1024];  // == S*n*D for all levels
__device__ __align__(256) __nv_bfloat16       g_yth[D * N_NODES];
__device__ __align__(256) __nv_bfloat16       g_ytl[D * N_NODES];

// ---------------- PTX helpers ----------------
__device__ __forceinline__ uint32_t smem_u32(const void* p) {
    uint32_t a;
    asm("{ .reg .u64 t; cvta.to.shared.u64 t, %1; cvt.u32.u64 %0, t; }" : "=r"(a) : "l"(p));
    return a;
}
__device__ __forceinline__ void cpasync16(uint32_t dst, const void* src) {
    asm volatile("cp.async.cg.shared.global [%0], [%1], 16;" :: "r"(dst), "l"(src));
}
__device__ __forceinline__ void ldsm4(uint32_t* r, uint32_t a) {
    asm volatile("ldmatrix.sync.aligned.m8n8.x4.shared.b16 {%0,%1,%2,%3}, [%4];"
                 : "=r"(r[0]), "=r"(r[1]), "=r"(r[2]), "=r"(r[3]) : "r"(a));
}
__device__ __forceinline__ void mma_bf16(float* c, const uint32_t* a, uint32_t b0, uint32_t b1) {
    asm volatile("mma.sync.aligned.m16n8k16.row.col.f32.bf16.bf16.f32 "
                 "{%0,%1,%2,%3}, {%4,%5,%6,%7}, {%8,%9}, {%0,%1,%2,%3};"
                 : "+f"(c[0]), "+f"(c[1]), "+f"(c[2]), "+f"(c[3])
                 : "r"(a[0]), "r"(a[1]), "r"(a[2]), "r"(a[3]), "r"(b0), "r"(b1));
}
__device__ __forceinline__ uint32_t pack_bf16x2(float a, float b) {
    __nv_bfloat162 t = __floats2bfloat162_rn(a, b);
    return *reinterpret_cast<uint32_t*>(&t);
}

// ---------------- score + sort key ----------------
__global__ void score_key_kernel(const float* __restrict__ x, const float* __restrict__ w,
                                 float* __restrict__ score, unsigned long long* __restrict__ key,
                                 int n) {
    int warp = threadIdx.x >> 5, lane = threadIdx.x & 31;
    int row = blockIdx.x * (blockDim.x >> 5) + warp;
    if (row >= n) return;
    float4 xv = reinterpret_cast<const float4*>(x + (size_t)row * D)[lane];
    float4 wv = reinterpret_cast<const float4*>(w)[lane];
    float d  = xv.x * wv.x + xv.y * wv.y + xv.z * wv.z + xv.w * wv.w;
    float ww = wv.x * wv.x + wv.y * wv.y + wv.z * wv.z + wv.w * wv.w;
    #pragma unroll
    for (int o = 16; o; o >>= 1) {
        d  += __shfl_xor_sync(0xffffffffu, d, o);
        ww += __shfl_xor_sync(0xffffffffu, ww, o);
    }
    if (lane == 0) {
        float s = tanhf(d / sqrtf(ww));
        score[row] = s;
        unsigned int b = __float_as_uint(s);
        b ^= (b & 0x80000000u) ? 0xFFFFFFFFu : 0x80000000u;
        unsigned int desc = ~b;
        key[row] = (((unsigned long long)desc) << 32) | (unsigned int)row;
    }
}

// ---------------- single-block bitonic sort ----------------
__global__ void bitonic_kernel(unsigned long long* __restrict__ key, int n) {
    extern __shared__ unsigned long long s[];
    for (int i = threadIdx.x; i < n; i += blockDim.x) s[i] = key[i];
    __syncthreads();
    for (int ksz = 2; ksz <= n; ksz <<= 1) {
        for (int j = ksz >> 1; j > 0; j >>= 1) {
            for (int i = threadIdx.x; i < n; i += blockDim.x) {
                int ixj = i ^ j;
                if (ixj > i) {
                    unsigned long long a = s[i], b = s[ixj];
                    bool up = ((i & ksz) == 0);
                    if ((a > b) == up) { s[i] = b; s[ixj] = a; }
                }
            }
            __syncthreads();
        }
    }
    for (int i = threadIdx.x; i < n; i += blockDim.x) key[i] = s[i];
}

// ---------------- gather rows + gate by score, emit perm ----------------
__global__ void gather_gate_kernel(const float* __restrict__ xin,
                                   const unsigned long long* __restrict__ key,
                                   const float* __restrict__ score,
                                   float* __restrict__ xout, int* __restrict__ perm, int k) {
    int i = blockIdx.x;
    int p = (int)(key[i] & 0xffffffffu);
    if (threadIdx.x == 0) perm[i] = p;
    float s = score[p];
    xout[(size_t)i * D + threadIdx.x] = xin[(size_t)p * D + threadIdx.x] * s;
}

// ---------------- H[perm][:,perm] -> bf16 hi/lo planes, row staging ----------------
__global__ void gatherH_rows(const float* __restrict__ H, const int* __restrict__ perm,
                             __nv_bfloat16* __restrict__ Hh, __nv_bfloat16* __restrict__ Hl,
                             int k) {
    extern __shared__ float sm[];
    float* rowf = sm;
    int* ps = (int*)(sm + N_NODES);
    int i = blockIdx.x;
    int pi = __ldg(&perm[i]);
    const float4* src = reinterpret_cast<const float4*>(H + (size_t)pi * N_NODES);
    float4* d4 = reinterpret_cast<float4*>(rowf);
    for (int j = threadIdx.x; j < N_NODES / 4; j += blockDim.x) d4[j] = src[j];
    for (int j = threadIdx.x; j < k; j += blockDim.x) ps[j] = __ldg(&perm[j]);
    __syncthreads();
    __nv_bfloat16* dh = Hh + (size_t)i * k;
    __nv_bfloat16* dl = Hl + (size_t)i * k;
    for (int j0 = threadIdx.x * 8; j0 < k; j0 += blockDim.x * 8) {
        uint32_t hv[4], lv[4];
        #pragma unroll
        for (int q = 0; q < 4; q++) {
            float v0 = rowf[ps[j0 + 2 * q]];
            float v1 = rowf[ps[j0 + 2 * q + 1]];
            float h0 = __bfloat162float(__float2bfloat16(v0));
            float h1 = __bfloat162float(__float2bfloat16(v1));
            hv[q] = pack_bf16x2(v0, v1);
            lv[q] = pack_bf16x2(v0 - h0, v1 - h1);
        }
        *reinterpret_cast<uint4*>(dh + j0) = make_uint4(hv[0], hv[1], hv[2], hv[3]);
        *reinterpret_cast<uint4*>(dl + j0) = make_uint4(lv[0], lv[1], lv[2], lv[3]);
    }
}

// ---------------- Yt = (X @ W + b)^T as bf16 hi/lo planes [128 x n] ----------------
__global__ void xw_trans_kernel(const float* __restrict__ X, const float* __restrict__ W,
                                const float* __restrict__ b,
                                __nv_bfloat16* __restrict__ Yh, __nv_bfloat16* __restrict__ Yl,
                                int n) {
    __shared__ float xs[16][D];
    int r0 = blockIdx.x * 16;
    int tid = threadIdx.x;
    #pragma unroll
    for (int r = 0; r < 16; r++) xs[r][tid] = X[(size_t)(r0 + r) * D + tid];
    __syncthreads();
    float bv = b[tid];
    float acc[16];
    #pragma unroll
    for (int r = 0; r < 16; r++) acc[r] = bv;
    #pragma unroll 4
    for (int kk = 0; kk < D; kk++) {
        float wv = W[kk * D + tid];
        #pragma unroll
        for (int r = 0; r < 16; r++) acc[r] += xs[r][kk] * wv;
    }
    #pragma unroll
    for (int r = 0; r < 16; r++) {
        float v = acc[r];
        __nv_bfloat16 h = __float2bfloat16(v);
        Yh[(size_t)tid * n + r0 + r] = h;
        Yl[(size_t)tid * n + r0 + r] = __float2bfloat16(v - __bfloat162float(h));
    }
}

// ---------------- mma.sync bf16 3-chain split-K GEMM ----------------
template <bool CONV>
__global__ void __launch_bounds__(256, CONV ? 1 : 2)
mma_gemm(const float* __restrict__ Afp,
         const __nv_bfloat16* __restrict__ Ahp, const __nv_bfloat16* __restrict__ Alp,
         const __nv_bfloat16* __restrict__ Bhp, const __nv_bfloat16* __restrict__ Blp,
         float* __restrict__ part, int n, int Kc) {
    extern __shared__ char dyn[];
    uint32_t base = (smem_u32(dyn) + 127) & ~127u;

    const int tid = threadIdx.x, lane = tid & 31, wid = tid >> 5;
    const int warp_m = wid & 3, warp_n = wid >> 2;
    const int rowTile = blockIdx.x * BM;
    const int kbase = blockIdx.y * Kc;
    const int nc = Kc / BK;

    const uint32_t oAh = 0, oAl = TILE_B, oBh = 2 * TILE_B, oBl = 3 * TILE_B;

    // A convert-path register staging
    const int a_row = tid >> 1;
    const int a_kh  = (tid & 1) * 16;
    float4 av[4];

    // B cp.async mapping: 2 chunks of 16B per thread per plane
    const int bj0 = (tid * 2) >> 2;
    const int bc0 = ((tid * 2) & 3) * 8;
    const int bj1 = (tid * 2 + 1) >> 2;
    const int bc1 = ((tid * 2 + 1) & 3) * 8;

    auto issue_stage = [&](int c) {
        uint32_t sb = base + (uint32_t)(c & 1) * STAGE_B;
        int kk = kbase + c * BK;
        cpasync16(sb + oBh + bj0 * (TSTRIDE * 2) + bc0 * 2, Bhp + (size_t)bj0 * n + kk + bc0);
        cpasync16(sb + oBh + bj1 * (TSTRIDE * 2) + bc1 * 2, Bhp + (size_t)bj1 * n + kk + bc1);
        cpasync16(sb + oBl + bj0 * (TSTRIDE * 2) + bc0 * 2, Blp + (size_t)bj0 * n + kk + bc0);
        cpasync16(sb + oBl + bj1 * (TSTRIDE * 2) + bc1 * 2, Blp + (size_t)bj1 * n + kk + bc1);
        if (!CONV) {
            cpasync16(sb + oAh + bj0 * (TSTRIDE * 2) + bc0 * 2, Ahp + (size_t)(rowTile + bj0) * n + kk + bc0);
            cpasync16(sb + oAh + bj1 * (TSTRIDE * 2) + bc1 * 2, Ahp + (size_t)(rowTile + bj1) * n + kk + bc1);
            cpasync16(sb + oAl + bj0 * (TSTRIDE * 2) + bc0 * 2, Alp + (size_t)(rowTile + bj0) * n + kk + bc0);
            cpasync16(sb + oAl + bj1 * (TSTRIDE * 2) + bc1 * 2, Alp + (size_t)(rowTile + bj1) * n + kk + bc1);
        }
        asm volatile("cp.async.commit_group;");
    };
    auto ldg_A = [&](int c) {
        if (CONV) {
            const float4* p = reinterpret_cast<const float4*>(
                Afp + (size_t)(rowTile + a_row) * n + kbase + c * BK + a_kh);
            #pragma unroll
            for (int q = 0; q < 4; q++) av[q] = p[q];
        }
    };
    auto sts_A = [&](int c) {
        if (CONV) {
            uint32_t sb = base + (uint32_t)(c & 1) * STAGE_B;
            uint32_t h[8], l[8];
            #pragma unroll
            for (int q = 0; q < 4; q++) {
                float hx = __bfloat162float(__float2bfloat16(av[q].x));
                float hy = __bfloat162float(__float2bfloat16(av[q].y));
                float hz = __bfloat162float(__float2bfloat16(av[q].z));
                float hw = __bfloat162float(__float2bfloat16(av[q].w));
                h[q * 2]     = pack_bf16x2(av[q].x, av[q].y);
                h[q * 2 + 1] = pack_bf16x2(av[q].z, av[q].w);
                l[q * 2]     = pack_bf16x2(av[q].x - hx, av[q].y - hy);
                l[q * 2 + 1] = pack_bf16x2(av[q].z - hz, av[q].w - hw);
            }
            uint32_t off = a_row * (TSTRIDE * 2) + a_kh * 2;
            asm volatile("st.shared.v4.b32 [%0], {%1,%2,%3,%4};"
                         :: "r"(sb + oAh + off), "r"(h[0]), "r"(h[1]), "r"(h[2]), "r"(h[3]));
            asm volatile("st.shared.v4.b32 [%0], {%1,%2,%3,%4};"
                         :: "r"(sb + oAh + off + 16), "r"(h[4]), "r"(h[5]), "r"(h[6]), "r"(h[7]));
            asm volatile("st.shared.v4.b32 [%0], {%1,%2,%3,%4};"
                         :: "r"(sb + oAl + off), "r"(l[0]), "r"(l[1]), "r"(l[2]), "r"(l[3]));
            asm volatile("st.shared.v4.b32 [%0], {%1,%2,%3,%4};"
                         :: "r"(sb + oAl + off + 16), "r"(l[4]), "r"(l[5]), "r"(l[6]), "r"(l[7]));
        }
    };

    float acc[2][8][4];
    #pragma unroll
    for (int i = 0; i < 2; i++)
        #pragma unroll
        for (int j = 0; j < 8; j++)
            #pragma unroll
            for (int q = 0; q < 4; q++) acc[i][j][q] = 0.f;

    const int lr = lane & 7, lsel = lane >> 3;

    issue_stage(0);
    ldg_A(0);
    sts_A(0);

    for (int c = 0; c < nc; c++) {
        uint32_t sb = base + (uint32_t)(c & 1) * STAGE_B;
        bool pf = (c + 1 < nc);
        __syncthreads();
        if (pf) { issue_stage(c + 1); ldg_A(c + 1); }
        if (pf) asm volatile("cp.async.wait_group 1;" ::: "memory");
        else    asm volatile("cp.async.wait_group 0;" ::: "memory");
        __syncthreads();

        #pragma unroll
        for (int ks = 0; ks < 2; ks++) {
            const int k16 = ks * 16;
            uint32_t Ahf[2][4], Alf[2][4];
            #pragma unroll
            for (int mf = 0; mf < 2; mf++) {
                int row = warp_m * 32 + mf * 16 + lr + (lsel & 1) * 8;
                int col = k16 + (lsel >> 1) * 8;
                uint32_t off = row * (TSTRIDE * 2) + col * 2;
                ldsm4(Ahf[mf], sb + oAh + off);
                ldsm4(Alf[mf], sb + oAl + off);
            }
            #pragma unroll
            for (int p = 0; p < 4; p++) {
                uint32_t Bhf[4], Blf[4];
                int row = warp_n * 64 + p * 16 + lr + (lsel >> 1) * 8;
                int col = k16 + (lsel & 1) * 8;
                uint32_t off = row * (TSTRIDE * 2) + col * 2;
                ldsm4(Bhf, sb + oBh + off);
                ldsm4(Blf, sb + oBl + off);
                #pragma unroll
                for (int mf = 0; mf < 2; mf++)
                    #pragma unroll
                    for (int s = 0; s < 2; s++) {
                        int nf = p * 2 + s;
                        mma_bf16(acc[mf][nf], Ahf[mf], Bhf[s * 2], Bhf[s * 2 + 1]);
                        mma_bf16(acc[mf][nf], Ahf[mf], Blf[s * 2], Blf[s * 2 + 1]);
                        mma_bf16(acc[mf][nf], Alf[mf], Bhf[s * 2], Bhf[s * 2 + 1]);
                    }
            }
        }
        if (pf) sts_A(c + 1);
    }

    float* Zp = part + (size_t)blockIdx.y * n * D;
    const int g = lane >> 2, cq = (lane & 3) * 2;
    #pragma unroll
    for (int mf = 0; mf < 2; mf++) {
        int row = rowTile + warp_m * 32 + mf * 16 + g;
        #pragma unroll
        for (int nf = 0; nf < 8; nf++) {
            int col = warp_n * 64 + nf * 8 + cq;
            *reinterpret_cast<float2*>(&Zp[(size_t)row * D + col]) =
                make_float2(acc[mf][nf][0], acc[mf][nf][1]);
            *reinterpret_cast<float2*>(&Zp[(size_t)(row + 8) * D + col]) =
                make_float2(acc[mf][nf][2], acc[mf][nf][3]);
        }
    }
}

// ---------------- deterministic partial reduction + relu ----------------
__global__ void reduce_relu_kernel(const float* __restrict__ Zpart, float* __restrict__ Z,
                                   int total, int SK) {
    int i = blockIdx.x * blockDim.x + threadIdx.x;
    if (i >= total) return;
    float s = 0.f;
    for (int p = 0; p < SK; p++) s += Zpart[(size_t)p * total + i];
    Z[i] = fmaxf(s, 0.f);
}

// ---------------- dst[perm[i]] += x[i] ----------------
__global__ void scatter_add_kernel(float* __restrict__ dst, const float* __restrict__ xsrc,
                                   const int* __restrict__ perm, int k) {
    int i = blockIdx.x;
    int p = perm[i];
    dst[(size_t)p * D + threadIdx.x] += xsrc[(size_t)i * D + threadIdx.x];
}

// ---------------- host orchestration ----------------
static inline int pick_sk(int n) {
    if (n >= 8192) return 4;
    if (n >= 4096) return 8;
    if (n >= 2048) return 16;
    return 32;
}

static void conv_relu(const float* Afp, const __nv_bfloat16* Ahp, const __nv_bfloat16* Alp,
                      const float* X, const float* W, const float* bias,
                      float* outp, int n, __nv_bfloat16* yth, __nv_bfloat16* ytl, float* part) {
    xw_trans_kernel<<<n / 16, 128>>>(X, W, bias, yth, ytl, n);
    int S = pick_sk(n);
    dim3 grid(n / BM, S);
    if (Afp)
        mma_gemm<true><<<grid, 256, GEMM_DYN>>>(Afp, nullptr, nullptr, yth, ytl, part, n, n / S);
    else
        mma_gemm<false><<<grid, 256, GEMM_DYN>>>(nullptr, Ahp, Alp, yth, ytl, part, n, n / S);
    int total = n * D;
    reduce_relu_kernel<<<(total + 255) / 256, 256>>>(part, outp, total, S);
}

extern "C" void kernel_launch(void* const* d_in, const int* in_sizes, int n_in,
                              void* d_out, int out_size) {
    const float* feat = (const float*)d_in[0];
    const float* H    = (const float*)d_in[1];
    const float* pw[3] = {(const float*)d_in[2], (const float*)d_in[3], (const float*)d_in[4]};
    const float* Wd[3] = {(const float*)d_in[5], (const float*)d_in[7], (const float*)d_in[9]};
    const float* bd[3] = {(const float*)d_in[6], (const float*)d_in[8], (const float*)d_in[10]};
    const float* Wu[3] = {(const float*)d_in[11], (const float*)d_in[13], (const float*)d_in[15]};
    const float* bu[3] = {(const float*)d_in[12], (const float*)d_in[14], (const float*)d_in[16]};
    float* out = (float*)d_out;

    float *score, *xA, *xB, *xs1, *xs2, *part;
    unsigned long long* key;
    int *perm0, *perm1, *perm2;
    __nv_bfloat16 *yth, *ytl, *Hg0h, *Hg0l, *Hg1h, *Hg1l, *Hg2h, *Hg2l;
    cudaGetSymbolAddress((void**)&score, g_score);
    cudaGetSymbolAddress((void**)&key,   g_key);
    cudaGetSymbolAddress((void**)&perm0, g_perm0);
    cudaGetSymbolAddress((void**)&perm1, g_perm1);
    cudaGetSymbolAddress((void**)&perm2, g_perm2);
    cudaGetSymbolAddress((void**)&xA,    g_xA);
    cudaGetSymbolAddress((void**)&xB,    g_xB);
    cudaGetSymbolAddress((void**)&xs1,   g_xs1);
    cudaGetSymbolAddress((void**)&xs2,   g_xs2);
    cudaGetSymbolAddress((void**)&part,  g_part);
    cudaGetSymbolAddress((void**)&yth,   g_yth);
    cudaGetSymbolAddress((void**)&ytl,   g_ytl);
    cudaGetSymbolAddress((void**)&Hg0h,  g_Hg0h);
    cudaGetSymbolAddress((void**)&Hg0l,  g_Hg0l);
    cudaGetSymbolAddress((void**)&Hg1h,  g_Hg1h);
    cudaGetSymbolAddress((void**)&Hg1l,  g_Hg1l);
    cudaGetSymbolAddress((void**)&Hg2h,  g_Hg2h);
    cudaGetSymbolAddress((void**)&Hg2l,  g_Hg2l);

    cudaFuncSetAttribute(bitonic_kernel, cudaFuncAttributeMaxDynamicSharedMemorySize, 65536);
    cudaFuncSetAttribute(gatherH_rows,   cudaFuncAttributeMaxDynamicSharedMemorySize, 65536);
    cudaFuncSetAttribute(mma_gemm<true>,  cudaFuncAttributeMaxDynamicSharedMemorySize, GEMM_DYN);
    cudaFuncSetAttribute(mma_gemm<false>, cudaFuncAttributeMaxDynamicSharedMemorySize, GEMM_DYN);

    // ---------------- DOWN level 0 : n=8192 -> k=4096 ----------------
    score_key_kernel<<<N_NODES / 4, 128>>>(feat, pw[0], score, key, N_NODES);
    bitonic_kernel<<<1, 1024, N_NODES * 8>>>(key, N_NODES);
    gather_gate_kernel<<<K0, 128>>>(feat, key, score, xA, perm0, K0);
    gatherH_rows<<<K0, 512, (N_NODES + K0) * 4>>>(H, perm0, Hg0h, Hg0l, K0);
    conv_relu(nullptr, Hg0h, Hg0l, xA, Wd[0], bd[0], xs1, K0, yth, ytl, part);

    // ---------------- DOWN level 1 : n=4096 -> k=2048 ----------------
    score_key_kernel<<<K0 / 4, 128>>>(xs1, pw[1], score, key, K0);
    bitonic_kernel<<<1, 1024, K0 * 8>>>(key, K0);
    gather_gate_kernel<<<K1, 128>>>(xs1, key, score, xA, perm1, K1);
    gatherH_rows<<<K1, 512, (N_NODES + K1) * 4>>>(H, perm1, Hg1h, Hg1l, K1);  // full-H index (bug preserved)
    conv_relu(nullptr, Hg1h, Hg1l, xA, Wd[1], bd[1], xs2, K1, yth, ytl, part);

    // ---------------- DOWN level 2 : n=2048 -> k=1024 ----------------
    score_key_kernel<<<K1 / 4, 128>>>(xs2, pw[2], score, key, K1);
    bitonic_kernel<<<1, 1024, K1 * 8>>>(key, K1);
    gather_gate_kernel<<<K2, 128>>>(xs2, key, score, xA, perm2, K2);
    gatherH_rows<<<K2, 512, (N_NODES + K2) * 4>>>(H, perm2, Hg2h, Hg2l, K2);
    conv_relu(nullptr, Hg2h, Hg2l, xA, Wd[2], bd[2], xB, K2, yth, ytl, part);

    // ---------------- UP i=0 (j=2): res=xs2(2048), graph=Hg1, perm2 ----------------
    cudaMemcpyAsync(xA, xs2, (size_t)K1 * D * sizeof(float), cudaMemcpyDeviceToDevice);
    scatter_add_kernel<<<K2, 128>>>(xA, xB, perm2, K2);
    conv_relu(nullptr, Hg1h, Hg1l, xA, Wu[0], bu[0], xB, K1, yth, ytl, part);

    // ---------------- UP i=1 (j=1): res=xs1(4096), graph=Hg0, perm1 ----------------
    cudaMemcpyAsync(xA, xs1, (size_t)K0 * D * sizeof(float), cudaMemcpyDeviceToDevice);
    scatter_add_kernel<<<K1, 128>>>(xA, xB, perm1, K1);
    conv_relu(nullptr, Hg0h, Hg0l, xA, Wu[1], bu[1], xB, K0, yth, ytl, part);

    // ---------------- UP i=2 (j=0): res=feat(8192), graph=H (fp32, convert), perm0 ----------------
    cudaMemcpyAsync(xA, feat, (size_t)N_NODES * D * sizeof(float), cudaMemcpyDeviceToDevice);
    scatter_add_kernel<<<K0, 128>>>(xA, xB, perm0, K0);
    conv_relu(H, nullptr, nullptr, xA, Wu[2], bu[2], out, N_NODES, yth, ytl, part);
}

// round 5
// speedup vs baseline: 1.7764x; 1.1854x over previous
#include <cuda_runtime.h>
#include <cuda_bf16.h>
#include <stdint.h>

#define N_NODES 8192
#define D 128
#define K0 4096
#define K1 2048
#define K2 1024

// GEMM tile config
#define BM 128
#define BN 128
#define BK 32
#define TSTRIDE 40                       // halfs per smem tile row (32 + 8 pad)
#define TILE_B (128 * TSTRIDE * 2)       // 10240 bytes per tile plane
#define STAGE_B (4 * TILE_B)             // Ah, Al, Bh, Bl
#define GEMM_DYN (2 * STAGE_B + 256)

#define SORT_TILE 2048

// ---------------- scratch (static __device__ arrays; no allocs) ----------------
__device__ __align__(256) float               g_score[N_NODES];
__device__ __align__(256) unsigned long long  g_key[N_NODES];
__device__ __align__(256) int                 g_perm0[K0];
__device__ __align__(256) int                 g_perm1[K1];
__device__ __align__(256) int                 g_perm2[K2];
__device__ __align__(256) float               g_xA[N_NODES * D];
__device__ __align__(256) float               g_xB[N_NODES * D];
__device__ __align__(256) float               g_xs1[K0 * D];
__device__ __align__(256) float               g_xs2[K1 * D];
__device__ __align__(256) __nv_bfloat16       g_Hg0h[(size_t)K0 * K0];
__device__ __align__(256) __nv_bfloat16       g_Hg0l[(size_t)K0 * K0];
__device__ __align__(256) __nv_bfloat16       g_Hg1h[(size_t)K1 * K1];
__device__ __align__(256) __nv_bfloat16       g_Hg1l[(size_t)K1 * K1];
__device__ __align__(256) __nv_bfloat16       g_Hg2h[(size_t)K2 * K2];
__device__ __align__(256) __nv_bfloat16       g_Hg2l[(size_t)K2 * K2];
__device__ __align__(256) float               g_part[4 * 1024 * 1024];
__device__ __align__(256) __nv_bfloat16       g_yth[D * N_NODES];
__device__ __align__(256) __nv_bfloat16       g_ytl[D * N_NODES];

// ---------------- PTX helpers ----------------
__device__ __forceinline__ uint32_t smem_u32(const void* p) {
    uint32_t a;
    asm("{ .reg .u64 t; cvta.to.shared.u64 t, %1; cvt.u32.u64 %0, t; }" : "=r"(a) : "l"(p));
    return a;
}
__device__ __forceinline__ void cpasync16(uint32_t dst, const void* src) {
    asm volatile("cp.async.cg.shared.global [%0], [%1], 16;" :: "r"(dst), "l"(src));
}
__device__ __forceinline__ void ldsm4(uint32_t* r, uint32_t a) {
    asm volatile("ldmatrix.sync.aligned.m8n8.x4.shared.b16 {%0,%1,%2,%3}, [%4];"
                 : "=r"(r[0]), "=r"(r[1]), "=r"(r[2]), "=r"(r[3]) : "r"(a));
}
__device__ __forceinline__ void mma_bf16(float* c, const uint32_t* a, uint32_t b0, uint32_t b1) {
    asm volatile("mma.sync.aligned.m16n8k16.row.col.f32.bf16.bf16.f32 "
                 "{%0,%1,%2,%3}, {%4,%5,%6,%7}, {%8,%9}, {%0,%1,%2,%3};"
                 : "+f"(c[0]), "+f"(c[1]), "+f"(c[2]), "+f"(c[3])
                 : "r"(a[0]), "r"(a[1]), "r"(a[2]), "r"(a[3]), "r"(b0), "r"(b1));
}
__device__ __forceinline__ uint32_t pack_bf16x2(float a, float b) {
    __nv_bfloat162 t = __floats2bfloat162_rn(a, b);
    return *reinterpret_cast<uint32_t*>(&t);
}

// ---------------- score + sort key ----------------
__global__ void score_key_kernel(const float* __restrict__ x, const float* __restrict__ w,
                                 float* __restrict__ score, unsigned long long* __restrict__ key,
                                 int n) {
    int warp = threadIdx.x >> 5, lane = threadIdx.x & 31;
    int row = blockIdx.x * (blockDim.x >> 5) + warp;
    if (row >= n) return;
    float4 xv = reinterpret_cast<const float4*>(x + (size_t)row * D)[lane];
    float4 wv = reinterpret_cast<const float4*>(w)[lane];
    float d  = xv.x * wv.x + xv.y * wv.y + xv.z * wv.z + xv.w * wv.w;
    float ww = wv.x * wv.x + wv.y * wv.y + wv.z * wv.z + wv.w * wv.w;
    #pragma unroll
    for (int o = 16; o; o >>= 1) {
        d  += __shfl_xor_sync(0xffffffffu, d, o);
        ww += __shfl_xor_sync(0xffffffffu, ww, o);
    }
    if (lane == 0) {
        float s = tanhf(d / sqrtf(ww));
        score[row] = s;
        unsigned int b = __float_as_uint(s);
        b ^= (b & 0x80000000u) ? 0xFFFFFFFFu : 0x80000000u;
        unsigned int desc = ~b;
        key[row] = (((unsigned long long)desc) << 32) | (unsigned int)row;
    }
}

// ---------------- tiled bitonic sort (exact same comparator network) ----------------
// local full sort of a 2048 tile; comparator directions from GLOBAL index.
__global__ void sort_local(unsigned long long* __restrict__ key) {
    __shared__ unsigned long long s[SORT_TILE];
    int tid = threadIdx.x;                      // 1024
    int base = blockIdx.x * SORT_TILE;
    s[tid] = key[base + tid];
    s[tid + 1024] = key[base + tid + 1024];
    __syncthreads();
    for (int ksz = 2; ksz <= SORT_TILE; ksz <<= 1) {
        for (int j = ksz >> 1; j > 0; j >>= 1) {
            int i = ((tid & ~(j - 1)) << 1) | (tid & (j - 1));
            int x = i | j;
            bool up = (((base + i) & ksz) == 0);
            unsigned long long a = s[i], b = s[x];
            if ((a > b) == up) { s[i] = b; s[x] = a; }
            __syncthreads();
        }
    }
    key[base + tid] = s[tid];
    key[base + tid + 1024] = s[tid + 1024];
}

// local merge phase: j = 1024 .. 1 within a tile, for a given ksz
__global__ void lmerge(unsigned long long* __restrict__ key, int ksz) {
    __shared__ unsigned long long s[SORT_TILE];
    int tid = threadIdx.x;
    int base = blockIdx.x * SORT_TILE;
    s[tid] = key[base + tid];
    s[tid + 1024] = key[base + tid + 1024];
    __syncthreads();
    for (int j = SORT_TILE >> 1; j > 0; j >>= 1) {
        int i = ((tid & ~(j - 1)) << 1) | (tid & (j - 1));
        int x = i | j;
        bool up = (((base + i) & ksz) == 0);
        unsigned long long a = s[i], b = s[x];
        if ((a > b) == up) { s[i] = b; s[x] = a; }
        __syncthreads();
    }
    key[base + tid] = s[tid];
    key[base + tid + 1024] = s[tid + 1024];
}

// global cross-tile compare-exchange: one pair per thread
__global__ void gmerge(unsigned long long* __restrict__ key, int ksz, int j) {
    int p = blockIdx.x * blockDim.x + threadIdx.x;
    int i = ((p & ~(j - 1)) << 1) | (p & (j - 1));
    int x = i | j;
    bool up = ((i & ksz) == 0);
    unsigned long long a = key[i], b = key[x];
    if ((a > b) == up) { key[i] = b; key[x] = a; }
}

static void run_sort(unsigned long long* key, int n) {
    sort_local<<<n / SORT_TILE, 1024>>>(key);
    for (int ksz = SORT_TILE * 2; ksz <= n; ksz <<= 1) {
        for (int j = ksz >> 1; j >= SORT_TILE; j >>= 1)
            gmerge<<<n / 512, 256>>>(key, ksz, j);
        lmerge<<<n / SORT_TILE, 1024>>>(key, ksz);
    }
}

// ---------------- gather rows + gate by score, emit perm ----------------
__global__ void gather_gate_kernel(const float* __restrict__ xin,
                                   const unsigned long long* __restrict__ key,
                                   const float* __restrict__ score,
                                   float* __restrict__ xout, int* __restrict__ perm, int k) {
    int i = blockIdx.x;
    int p = (int)(key[i] & 0xffffffffu);
    if (threadIdx.x == 0) perm[i] = p;
    float s = score[p];
    xout[(size_t)i * D + threadIdx.x] = xin[(size_t)p * D + threadIdx.x] * s;
}

// ---------------- H[perm][:,perm] -> bf16 hi/lo planes, row staging ----------------
__global__ void gatherH_rows(const float* __restrict__ H, const int* __restrict__ perm,
                             __nv_bfloat16* __restrict__ Hh, __nv_bfloat16* __restrict__ Hl,
                             int k) {
    extern __shared__ float sm[];
    float* rowf = sm;
    int* ps = (int*)(sm + N_NODES);
    int i = blockIdx.x;
    int pi = __ldg(&perm[i]);
    const float4* src = reinterpret_cast<const float4*>(H + (size_t)pi * N_NODES);
    float4* d4 = reinterpret_cast<float4*>(rowf);
    for (int j = threadIdx.x; j < N_NODES / 4; j += blockDim.x) d4[j] = src[j];
    for (int j = threadIdx.x; j < k; j += blockDim.x) ps[j] = __ldg(&perm[j]);
    __syncthreads();
    __nv_bfloat16* dh = Hh + (size_t)i * k;
    __nv_bfloat16* dl = Hl + (size_t)i * k;
    for (int j0 = threadIdx.x * 8; j0 < k; j0 += blockDim.x * 8) {
        uint32_t hv[4], lv[4];
        #pragma unroll
        for (int q = 0; q < 4; q++) {
            float v0 = rowf[ps[j0 + 2 * q]];
            float v1 = rowf[ps[j0 + 2 * q + 1]];
            float h0 = __bfloat162float(__float2bfloat16(v0));
            float h1 = __bfloat162float(__float2bfloat16(v1));
            hv[q] = pack_bf16x2(v0, v1);
            lv[q] = pack_bf16x2(v0 - h0, v1 - h1);
        }
        *reinterpret_cast<uint4*>(dh + j0) = make_uint4(hv[0], hv[1], hv[2], hv[3]);
        *reinterpret_cast<uint4*>(dl + j0) = make_uint4(lv[0], lv[1], lv[2], lv[3]);
    }
}

// ---------------- Yt = (X @ W + b)^T as bf16 hi/lo planes [128 x n] ----------------
__global__ void xw_trans_kernel(const float* __restrict__ X, const float* __restrict__ W,
                                const float* __restrict__ b,
                                __nv_bfloat16* __restrict__ Yh, __nv_bfloat16* __restrict__ Yl,
                                int n) {
    __shared__ float xs[16][D];
    int r0 = blockIdx.x * 16;
    int tid = threadIdx.x;
    #pragma unroll
    for (int r = 0; r < 16; r++) xs[r][tid] = X[(size_t)(r0 + r) * D + tid];
    __syncthreads();
    float bv = b[tid];
    float acc[16];
    #pragma unroll
    for (int r = 0; r < 16; r++) acc[r] = bv;
    #pragma unroll 4
    for (int kk = 0; kk < D; kk++) {
        float wv = W[kk * D + tid];
        #pragma unroll
        for (int r = 0; r < 16; r++) acc[r] += xs[r][kk] * wv;
    }
    #pragma unroll
    for (int r = 0; r < 16; r++) {
        float v = acc[r];
        __nv_bfloat16 h = __float2bfloat16(v);
        Yh[(size_t)tid * n + r0 + r] = h;
        Yl[(size_t)tid * n + r0 + r] = __float2bfloat16(v - __bfloat162float(h));
    }
}

// ---------------- mma.sync bf16 3-chain split-K GEMM ----------------
template <bool CONV>
__global__ void __launch_bounds__(256, 2)
mma_gemm(const float* __restrict__ Afp,
         const __nv_bfloat16* __restrict__ Ahp, const __nv_bfloat16* __restrict__ Alp,
         const __nv_bfloat16* __restrict__ Bhp, const __nv_bfloat16* __restrict__ Blp,
         float* __restrict__ part, int n, int Kc) {
    extern __shared__ char dyn[];
    uint32_t base = (smem_u32(dyn) + 127) & ~127u;

    const int tid = threadIdx.x, lane = tid & 31, wid = tid >> 5;
    const int warp_m = wid & 3, warp_n = wid >> 2;
    const int rowTile = blockIdx.x * BM;
    const int kbase = blockIdx.y * Kc;
    const int nc = Kc / BK;

    const uint32_t oAh = 0, oAl = TILE_B, oBh = 2 * TILE_B, oBl = 3 * TILE_B;

    const int a_row = tid >> 1;
    const int a_kh  = (tid & 1) * 16;
    float4 av[4];

    const int bj0 = (tid * 2) >> 2;
    const int bc0 = ((tid * 2) & 3) * 8;
    const int bj1 = (tid * 2 + 1) >> 2;
    const int bc1 = ((tid * 2 + 1) & 3) * 8;

    auto issue_stage = [&](int c) {
        uint32_t sb = base + (uint32_t)(c & 1) * STAGE_B;
        int kk = kbase + c * BK;
        cpasync16(sb + oBh + bj0 * (TSTRIDE * 2) + bc0 * 2, Bhp + (size_t)bj0 * n + kk + bc0);
        cpasync16(sb + oBh + bj1 * (TSTRIDE * 2) + bc1 * 2, Bhp + (size_t)bj1 * n + kk + bc1);
        cpasync16(sb + oBl + bj0 * (TSTRIDE * 2) + bc0 * 2, Blp + (size_t)bj0 * n + kk + bc0);
        cpasync16(sb + oBl + bj1 * (TSTRIDE * 2) + bc1 * 2, Blp + (size_t)bj1 * n + kk + bc1);
        if (!CONV) {
            cpasync16(sb + oAh + bj0 * (TSTRIDE * 2) + bc0 * 2, Ahp + (size_t)(rowTile + bj0) * n + kk + bc0);
            cpasync16(sb + oAh + bj1 * (TSTRIDE * 2) + bc1 * 2, Ahp + (size_t)(rowTile + bj1) * n + kk + bc1);
            cpasync16(sb + oAl + bj0 * (TSTRIDE * 2) + bc0 * 2, Alp + (size_t)(rowTile + bj0) * n + kk + bc0);
            cpasync16(sb + oAl + bj1 * (TSTRIDE * 2) + bc1 * 2, Alp + (size_t)(rowTile + bj1) * n + kk + bc1);
        }
        asm volatile("cp.async.commit_group;");
    };
    auto ldg_A = [&](int c) {
        if (CONV) {
            const float4* p = reinterpret_cast<const float4*>(
                Afp + (size_t)(rowTile + a_row) * n + kbase + c * BK + a_kh);
            #pragma unroll
            for (int q = 0; q < 4; q++) av[q] = p[q];
        }
    };
    auto sts_A = [&](int c) {
        if (CONV) {
            uint32_t sb = base + (uint32_t)(c & 1) * STAGE_B;
            uint32_t off = a_row * (TSTRIDE * 2) + a_kh * 2;
            #pragma unroll
            for (int half = 0; half < 2; half++) {
                uint32_t h[4], l[4];
                #pragma unroll
                for (int q = 0; q < 2; q++) {
                    const float4 v = av[half * 2 + q];
                    float hx = __bfloat162float(__float2bfloat16(v.x));
                    float hy = __bfloat162float(__float2bfloat16(v.y));
                    float hz = __bfloat162float(__float2bfloat16(v.z));
                    float hw = __bfloat162float(__float2bfloat16(v.w));
                    h[q * 2]     = pack_bf16x2(v.x, v.y);
                    h[q * 2 + 1] = pack_bf16x2(v.z, v.w);
                    l[q * 2]     = pack_bf16x2(v.x - hx, v.y - hy);
                    l[q * 2 + 1] = pack_bf16x2(v.z - hz, v.w - hw);
                }
                asm volatile("st.shared.v4.b32 [%0], {%1,%2,%3,%4};"
                             :: "r"(sb + oAh + off + half * 16), "r"(h[0]), "r"(h[1]), "r"(h[2]), "r"(h[3]));
                asm volatile("st.shared.v4.b32 [%0], {%1,%2,%3,%4};"
                             :: "r"(sb + oAl + off + half * 16), "r"(l[0]), "r"(l[1]), "r"(l[2]), "r"(l[3]));
            }
        }
    };

    float acc[2][8][4];
    #pragma unroll
    for (int i = 0; i < 2; i++)
        #pragma unroll
        for (int j = 0; j < 8; j++)
            #pragma unroll
            for (int q = 0; q < 4; q++) acc[i][j][q] = 0.f;

    const int lr = lane & 7, lsel = lane >> 3;

    issue_stage(0);
    ldg_A(0);
    sts_A(0);

    for (int c = 0; c < nc; c++) {
        uint32_t sb = base + (uint32_t)(c & 1) * STAGE_B;
        bool pf = (c + 1 < nc);
        __syncthreads();
        if (pf) { issue_stage(c + 1); ldg_A(c + 1); }
        if (pf) asm volatile("cp.async.wait_group 1;" ::: "memory");
        else    asm volatile("cp.async.wait_group 0;" ::: "memory");
        __syncthreads();

        #pragma unroll
        for (int ks = 0; ks < 2; ks++) {
            const int k16 = ks * 16;
            uint32_t Ahf[2][4], Alf[2][4];
            #pragma unroll
            for (int mf = 0; mf < 2; mf++) {
                int row = warp_m * 32 + mf * 16 + lr + (lsel & 1) * 8;
                int col = k16 + (lsel >> 1) * 8;
                uint32_t off = row * (TSTRIDE * 2) + col * 2;
                ldsm4(Ahf[mf], sb + oAh + off);
                ldsm4(Alf[mf], sb + oAl + off);
            }
            #pragma unroll
            for (int p = 0; p < 4; p++) {
                uint32_t Bhf[4], Blf[4];
                int row = warp_n * 64 + p * 16 + lr + (lsel >> 1) * 8;
                int col = k16 + (lsel & 1) * 8;
                uint32_t off = row * (TSTRIDE * 2) + col * 2;
                ldsm4(Bhf, sb + oBh + off);
                ldsm4(Blf, sb + oBl + off);
                #pragma unroll
                for (int mf = 0; mf < 2; mf++)
                    #pragma unroll
                    for (int s = 0; s < 2; s++) {
                        int nf = p * 2 + s;
                        mma_bf16(acc[mf][nf], Ahf[mf], Bhf[s * 2], Bhf[s * 2 + 1]);
                        mma_bf16(acc[mf][nf], Ahf[mf], Blf[s * 2], Blf[s * 2 + 1]);
                        mma_bf16(acc[mf][nf], Alf[mf], Bhf[s * 2], Bhf[s * 2 + 1]);
                    }
            }
        }
        if (pf) sts_A(c + 1);
    }

    float* Zp = part + (size_t)blockIdx.y * n * D;
    const int g = lane >> 2, cq = (lane & 3) * 2;
    #pragma unroll
    for (int mf = 0; mf < 2; mf++) {
        int row = rowTile + warp_m * 32 + mf * 16 + g;
        #pragma unroll
        for (int nf = 0; nf < 8; nf++) {
            int col = warp_n * 64 + nf * 8 + cq;
            *reinterpret_cast<float2*>(&Zp[(size_t)row * D + col]) =
                make_float2(acc[mf][nf][0], acc[mf][nf][1]);
            *reinterpret_cast<float2*>(&Zp[(size_t)(row + 8) * D + col]) =
                make_float2(acc[mf][nf][2], acc[mf][nf][3]);
        }
    }
}

// ---------------- deterministic partial reduction + relu ----------------
__global__ void reduce_relu_kernel(const float* __restrict__ Zpart, float* __restrict__ Z,
                                   int total, int SK) {
    int i = blockIdx.x * blockDim.x + threadIdx.x;
    if (i >= total) return;
    float s = 0.f;
    for (int p = 0; p < SK; p++) s += Zpart[(size_t)p * total + i];
    Z[i] = fmaxf(s, 0.f);
}

// ---------------- dst[perm[i]] += x[i] ----------------
__global__ void scatter_add_kernel(float* __restrict__ dst, const float* __restrict__ xsrc,
                                   const int* __restrict__ perm, int k) {
    int i = blockIdx.x;
    int p = perm[i];
    dst[(size_t)p * D + threadIdx.x] += xsrc[(size_t)i * D + threadIdx.x];
}

// ---------------- host orchestration ----------------
static inline int pick_sk(int n) {
    if (n >= 8192) return 4;
    if (n >= 4096) return 8;
    if (n >= 2048) return 16;
    return 32;
}

static void conv_relu(const float* Afp, const __nv_bfloat16* Ahp, const __nv_bfloat16* Alp,
                      const float* X, const float* W, const float* bias,
                      float* outp, int n, __nv_bfloat16* yth, __nv_bfloat16* ytl, float* part) {
    xw_trans_kernel<<<n / 16, 128>>>(X, W, bias, yth, ytl, n);
    int S = pick_sk(n);
    dim3 grid(n / BM, S);
    if (Afp)
        mma_gemm<true><<<grid, 256, GEMM_DYN>>>(Afp, nullptr, nullptr, yth, ytl, part, n, n / S);
    else
        mma_gemm<false><<<grid, 256, GEMM_DYN>>>(nullptr, Ahp, Alp, yth, ytl, part, n, n / S);
    int total = n * D;
    reduce_relu_kernel<<<(total + 255) / 256, 256>>>(part, outp, total, S);
}

extern "C" void kernel_launch(void* const* d_in, const int* in_sizes, int n_in,
                              void* d_out, int out_size) {
    const float* feat = (const float*)d_in[0];
    const float* H    = (const float*)d_in[1];
    const float* pw[3] = {(const float*)d_in[2], (const float*)d_in[3], (const float*)d_in[4]};
    const float* Wd[3] = {(const float*)d_in[5], (const float*)d_in[7], (const float*)d_in[9]};
    const float* bd[3] = {(const float*)d_in[6], (const float*)d_in[8], (const float*)d_in[10]};
    const float* Wu[3] = {(const float*)d_in[11], (const float*)d_in[13], (const float*)d_in[15]};
    const float* bu[3] = {(const float*)d_in[12], (const float*)d_in[14], (const float*)d_in[16]};
    float* out = (float*)d_out;

    float *score, *xA, *xB, *xs1, *xs2, *part;
    unsigned long long* key;
    int *perm0, *perm1, *perm2;
    __nv_bfloat16 *yth, *ytl, *Hg0h, *Hg0l, *Hg1h, *Hg1l, *Hg2h, *Hg2l;
    cudaGetSymbolAddress((void**)&score, g_score);
    cudaGetSymbolAddress((void**)&key,   g_key);
    cudaGetSymbolAddress((void**)&perm0, g_perm0);
    cudaGetSymbolAddress((void**)&perm1, g_perm1);
    cudaGetSymbolAddress((void**)&perm2, g_perm2);
    cudaGetSymbolAddress((void**)&xA,    g_xA);
    cudaGetSymbolAddress((void**)&xB,    g_xB);
    cudaGetSymbolAddress((void**)&xs1,   g_xs1);
    cudaGetSymbolAddress((void**)&xs2,   g_xs2);
    cudaGetSymbolAddress((void**)&part,  g_part);
    cudaGetSymbolAddress((void**)&yth,   g_yth);
    cudaGetSymbolAddress((void**)&ytl,   g_ytl);
    cudaGetSymbolAddress((void**)&Hg0h,  g_Hg0h);
    cudaGetSymbolAddress((void**)&Hg0l,  g_Hg0l);
    cudaGetSymbolAddress((void**)&Hg1h,  g_Hg1h);
    cudaGetSymbolAddress((void**)&Hg1l,  g_Hg1l);
    cudaGetSymbolAddress((void**)&Hg2h,  g_Hg2h);
    cudaGetSymbolAddress((void**)&Hg2l,  g_Hg2l);

    cudaFuncSetAttribute(gatherH_rows,   cudaFuncAttributeMaxDynamicSharedMemorySize, 65536);
    cudaFuncSetAttribute(mma_gemm<true>,  cudaFuncAttributeMaxDynamicSharedMemorySize, GEMM_DYN);
    cudaFuncSetAttribute(mma_gemm<false>, cudaFuncAttributeMaxDynamicSharedMemorySize, GEMM_DYN);

    // ---------------- DOWN level 0 : n=8192 -> k=4096 ----------------
    score_key_kernel<<<N_NODES / 4, 128>>>(feat, pw[0], score, key, N_NODES);
    run_sort(key, N_NODES);
    gather_gate_kernel<<<K0, 128>>>(feat, key, score, xA, perm0, K0);
    gatherH_rows<<<K0, 512, (N_NODES + K0) * 4>>>(H, perm0, Hg0h, Hg0l, K0);
    conv_relu(nullptr, Hg0h, Hg0l, xA, Wd[0], bd[0], xs1, K0, yth, ytl, part);

    // ---------------- DOWN level 1 : n=4096 -> k=2048 ----------------
    score_key_kernel<<<K0 / 4, 128>>>(xs1, pw[1], score, key, K0);
    run_sort(key, K0);
    gather_gate_kernel<<<K1, 128>>>(xs1, key, score, xA, perm1, K1);
    gatherH_rows<<<K1, 512, (N_NODES + K1) * 4>>>(H, perm1, Hg1h, Hg1l, K1);  // full-H index (bug preserved)
    conv_relu(nullptr, Hg1h, Hg1l, xA, Wd[1], bd[1], xs2, K1, yth, ytl, part);

    // ---------------- DOWN level 2 : n=2048 -> k=1024 ----------------
    score_key_kernel<<<K1 / 4, 128>>>(xs2, pw[2], score, key, K1);
    run_sort(key, K1);
    gather_gate_kernel<<<K2, 128>>>(xs2, key, score, xA, perm2, K2);
    gatherH_rows<<<K2, 512, (N_NODES + K2) * 4>>>(H, perm2, Hg2h, Hg2l, K2);
    conv_relu(nullptr, Hg2h, Hg2l, xA, Wd[2], bd[2], xB, K2, yth, ytl, part);

    // ---------------- UP i=0 (j=2): res=xs2(2048), graph=Hg1, perm2 ----------------
    cudaMemcpyAsync(xA, xs2, (size_t)K1 * D * sizeof(float), cudaMemcpyDeviceToDevice);
    scatter_add_kernel<<<K2, 128>>>(xA, xB, perm2, K2);
    conv_relu(nullptr, Hg1h, Hg1l, xA, Wu[0], bu[0], xB, K1, yth, ytl, part);

    // ---------------- UP i=1 (j=1): res=xs1(4096), graph=Hg0, perm1 ----------------
    cudaMemcpyAsync(xA, xs1, (size_t)K0 * D * sizeof(float), cudaMemcpyDeviceToDevice);
    scatter_add_kernel<<<K1, 128>>>(xA, xB, perm1, K1);
    conv_relu(nullptr, Hg0h, Hg0l, xA, Wu[1], bu[1], xB, K0, yth, ytl, part);

    // ---------------- UP i=2 (j=0): res=feat(8192), graph=H (fp32, convert), perm0 ----------------
    cudaMemcpyAsync(xA, feat, (size_t)N_NODES * D * sizeof(float), cudaMemcpyDeviceToDevice);
    scatter_add_kernel<<<K0, 128>>>(xA, xB, perm0, K0);
    conv_relu(H, nullptr, nullptr, xA, Wu[2], bu[2], out, N_NODES, yth, ytl, part);
}